// round 14
// baseline (speedup 1.0000x reference)
#include <cuda_runtime.h>
#include <cstdint>
#include <math.h>

#define T_TOK 8192
#define D_DIM 7168
#define E_EXP 256
#define K_TOP 8
#define G_GRP 8
#define LG_GRP 4

#define BM 128
#define BN 128
#define BK 16
#define PAD 132   // padded smem row (floats) to dodge bank conflicts

__device__ float g_logits[(size_t)T_TOK * E_EXP];

// ---------------- packed f32x2 helpers ----------------
__device__ __forceinline__ uint64_t pack2(float lo, float hi) {
    uint64_t r;
    asm("mov.b64 %0, {%1, %2};" : "=l"(r) : "r"(__float_as_uint(lo)), "r"(__float_as_uint(hi)));
    return r;
}
__device__ __forceinline__ void ffma2(uint64_t& d, uint64_t a, uint64_t b) {
    asm("fma.rn.f32x2 %0, %1, %2, %0;" : "+l"(d) : "l"(a), "l"(b));
}
__device__ __forceinline__ float2 unpack2(uint64_t v) {
    uint32_t lo, hi;
    asm("mov.b64 {%0, %1}, %2;" : "=r"(lo), "=r"(hi) : "l"(v));
    float2 f; f.x = __uint_as_float(lo); f.y = __uint_as_float(hi);
    return f;
}

// ---------------- GEMM: byte-identical to R13 (session best) ----------------
__global__ __launch_bounds__(256, 1)
void gemm_kernel(const float* __restrict__ A,   // x [T, D]
                 const float* __restrict__ B,   // W [E, D]
                 float* __restrict__ C,         // logits [T, E]
                 void* __restrict__ cnt_out,
                 int mode)
{
    __shared__ float As[BK][PAD];
    __shared__ float Bs[BK][PAD];

    const int tid = threadIdx.x;

    // fold-in: zero the counts output region (route launches after this kernel)
    if (blockIdx.x == 0 && blockIdx.y == 0) {
        if (mode == 2) ((float*)cnt_out)[tid] = 0.0f;
        else           ((int*)cnt_out)[tid]   = 0;
    }

    const int tx = tid & 15;
    const int ty = tid >> 4;
    const int tile_n = blockIdx.x;
    const int tile_m = blockIdx.y;

    const float* Ab = A + (size_t)tile_m * BM * D_DIM;
    const float* Bb = B + (size_t)tile_n * BN * D_DIM;

    const int lr = tid >> 2;
    const int lc = (tid & 3) * 4;

    uint64_t acc[8][4];
    #pragma unroll
    for (int i = 0; i < 8; i++)
        #pragma unroll
        for (int j = 0; j < 4; j++) acc[i][j] = 0ull;

    float4 a0 = *(const float4*)(Ab + (size_t)lr * D_DIM + lc);
    float4 a1 = *(const float4*)(Ab + (size_t)(lr + 64) * D_DIM + lc);
    float4 b0 = *(const float4*)(Bb + (size_t)lr * D_DIM + lc);
    float4 b1 = *(const float4*)(Bb + (size_t)(lr + 64) * D_DIM + lc);

    for (int k0 = 0; k0 < D_DIM; k0 += BK) {
        __syncthreads();
        As[lc + 0][lr] = a0.x; As[lc + 1][lr] = a0.y; As[lc + 2][lr] = a0.z; As[lc + 3][lr] = a0.w;
        As[lc + 0][lr + 64] = a1.x; As[lc + 1][lr + 64] = a1.y; As[lc + 2][lr + 64] = a1.z; As[lc + 3][lr + 64] = a1.w;
        Bs[lc + 0][lr] = b0.x; Bs[lc + 1][lr] = b0.y; Bs[lc + 2][lr] = b0.z; Bs[lc + 3][lr] = b0.w;
        Bs[lc + 0][lr + 64] = b1.x; Bs[lc + 1][lr + 64] = b1.y; Bs[lc + 2][lr + 64] = b1.z; Bs[lc + 3][lr + 64] = b1.w;
        __syncthreads();

        const int kn = k0 + BK;
        if (kn < D_DIM) {
            a0 = *(const float4*)(Ab + (size_t)lr * D_DIM + kn + lc);
            a1 = *(const float4*)(Ab + (size_t)(lr + 64) * D_DIM + kn + lc);
            b0 = *(const float4*)(Bb + (size_t)lr * D_DIM + kn + lc);
            b1 = *(const float4*)(Bb + (size_t)(lr + 64) * D_DIM + kn + lc);
        }

        #pragma unroll
        for (int kk = 0; kk < BK; kk++) {
            float4 av0 = *(const float4*)&As[kk][ty * 8];
            float4 av1 = *(const float4*)&As[kk][ty * 8 + 4];
            float4 bv0 = *(const float4*)&Bs[kk][tx * 8];
            float4 bv1 = *(const float4*)&Bs[kk][tx * 8 + 4];
            uint64_t bp[4];
            bp[0] = pack2(bv0.x, bv0.y);
            bp[1] = pack2(bv0.z, bv0.w);
            bp[2] = pack2(bv1.x, bv1.y);
            bp[3] = pack2(bv1.z, bv1.w);
            float av[8] = {av0.x, av0.y, av0.z, av0.w, av1.x, av1.y, av1.z, av1.w};
            #pragma unroll
            for (int i = 0; i < 8; i++) {
                uint64_t ap = pack2(av[i], av[i]);
                #pragma unroll
                for (int j = 0; j < 4; j++) ffma2(acc[i][j], ap, bp[j]);
            }
        }
    }

    const int row0 = tile_m * BM + ty * 8;
    const int col0 = tile_n * BN + tx * 8;
    #pragma unroll
    for (int i = 0; i < 8; i++) {
        float2 c0 = unpack2(acc[i][0]);
        float2 c1 = unpack2(acc[i][1]);
        float2 c2 = unpack2(acc[i][2]);
        float2 c3 = unpack2(acc[i][3]);
        float* cp = C + (size_t)(row0 + i) * E_EXP + col0;
        *(float4*)(cp)     = make_float4(c0.x, c0.y, c1.x, c1.y);
        *(float4*)(cp + 4) = make_float4(c2.x, c2.y, c3.x, c3.y);
    }
}

// ---------------- Routing: one warp per token, bitonic top-8 merge ----------------
// total order: (v desc, idx asc)  — matches jax top_k tie behavior
__device__ __forceinline__ bool gt_vi(float v1, int i1, float v2, int i2) {
    return (v1 > v2) || (v1 == v2 && i1 < i2);
}
__device__ __forceinline__ void ce_vi(float& va, int& ia, float& vb, int& ib) {
    // after: (va,ia) >= (vb,ib) in the total order
    bool sw = !gt_vi(va, ia, vb, ib);
    float vt = sw ? vb : va;  int it = sw ? ib : ia;
    vb = sw ? va : vb;        ib = sw ? ia : ib;
    va = vt;                  ia = it;
}

__global__ __launch_bounds__(256)
void route_kernel(const float* __restrict__ logits,
                  const float* __restrict__ bias,
                  void* __restrict__ w_out,
                  void* __restrict__ idx_out,
                  void* __restrict__ cnt_out,
                  int mode)
{
    const float NEG_INF = __int_as_float(0xff800000);
    const int warp = threadIdx.x >> 5;
    const int lane = threadIdx.x & 31;
    const int t = blockIdx.x * 8 + warp;
    if (t >= T_TOK) return;

    const float* lp = logits + (size_t)t * E_EXP;

    float v[8];   // biased scores (routing)
    #pragma unroll
    for (int r = 0; r < 8; r++) {
        float z = __ldg(lp + r * 32 + lane);
        float sig = 1.0f / (1.0f + expf(-z));
        v[r] = sig + __ldg(bias + r * 32 + lane);
    }

    // group scores: sum of top-2 biased scores per group (group r = reg r) — proven
    float gsc[8];
    #pragma unroll
    for (int r = 0; r < 8; r++) {
        float m1 = v[r], m2 = NEG_INF;
        #pragma unroll
        for (int off = 16; off; off >>= 1) {
            float o1 = __shfl_xor_sync(0xffffffffu, m1, off);
            float o2 = __shfl_xor_sync(0xffffffffu, m2, off);
            float hi = fmaxf(m1, o1);
            float lo = fminf(m1, o1);
            m2 = fmaxf(lo, fmaxf(m2, o2));
            m1 = hi;
        }
        gsc[r] = m1 + m2;
    }

    // top-LG groups (ties -> lower group index) — proven
    unsigned chosen = 0;
    #pragma unroll
    for (int it = 0; it < LG_GRP; it++) {
        float best = NEG_INF; int bg = 0;
        #pragma unroll
        for (int g = 0; g < G_GRP; g++) {
            bool free_g = ((chosen >> g) & 1u) == 0u;
            if (free_g && gsc[g] > best) { best = gsc[g]; bg = g; }
        }
        chosen |= 1u << bg;
    }

    // per-lane (v, idx) list, masked; ids unique across warp
    float sv[8]; int si[8];
    #pragma unroll
    for (int r = 0; r < 8; r++) {
        sv[r] = ((chosen >> r) & 1u) ? v[r] : NEG_INF;
        si[r] = r * 32 + lane;
    }

    // sort 8 descending — Batcher odd-even merge network (19 CEs)
    ce_vi(sv[0],si[0],sv[1],si[1]); ce_vi(sv[2],si[2],sv[3],si[3]);
    ce_vi(sv[4],si[4],sv[5],si[5]); ce_vi(sv[6],si[6],sv[7],si[7]);
    ce_vi(sv[0],si[0],sv[2],si[2]); ce_vi(sv[1],si[1],sv[3],si[3]);
    ce_vi(sv[4],si[4],sv[6],si[6]); ce_vi(sv[5],si[5],sv[7],si[7]);
    ce_vi(sv[1],si[1],sv[2],si[2]); ce_vi(sv[5],si[5],sv[6],si[6]);
    ce_vi(sv[0],si[0],sv[4],si[4]); ce_vi(sv[1],si[1],sv[5],si[5]);
    ce_vi(sv[2],si[2],sv[6],si[6]); ce_vi(sv[3],si[3],sv[7],si[7]);
    ce_vi(sv[2],si[2],sv[4],si[4]); ce_vi(sv[3],si[3],sv[5],si[5]);
    ce_vi(sv[1],si[1],sv[2],si[2]); ce_vi(sv[3],si[3],sv[4],si[4]);
    ce_vi(sv[5],si[5],sv[6],si[6]);

    // 5 butterfly steps: merge sorted-8 lists, keep top-8 (bitonic split + clean)
    #pragma unroll
    for (int off = 16; off; off >>= 1) {
        float ov[8]; int oi[8];
        #pragma unroll
        for (int j = 0; j < 8; j++) {
            ov[j] = __shfl_xor_sync(0xffffffffu, sv[j], off);
            oi[j] = __shfl_xor_sync(0xffffffffu, si[j], off);
        }
        // bitonic split: m[j] = max(a[j], b[7-j]) -> top-8 of union, bitonic
        float mv[8]; int mi[8];
        #pragma unroll
        for (int j = 0; j < 8; j++) {
            bool keep = gt_vi(sv[j], si[j], ov[7 - j], oi[7 - j]);
            mv[j] = keep ? sv[j] : ov[7 - j];
            mi[j] = keep ? si[j] : oi[7 - j];
        }
        // bitonic clean: distances 4, 2, 1 (12 CEs)
        ce_vi(mv[0],mi[0],mv[4],mi[4]); ce_vi(mv[1],mi[1],mv[5],mi[5]);
        ce_vi(mv[2],mi[2],mv[6],mi[6]); ce_vi(mv[3],mi[3],mv[7],mi[7]);
        ce_vi(mv[0],mi[0],mv[2],mi[2]); ce_vi(mv[1],mi[1],mv[3],mi[3]);
        ce_vi(mv[4],mi[4],mv[6],mi[6]); ce_vi(mv[5],mi[5],mv[7],mi[7]);
        ce_vi(mv[0],mi[0],mv[1],mi[1]); ce_vi(mv[2],mi[2],mv[3],mi[3]);
        ce_vi(mv[4],mi[4],mv[5],mi[5]); ce_vi(mv[6],mi[6],mv[7],mi[7]);
        #pragma unroll
        for (int j = 0; j < 8; j++) { sv[j] = mv[j]; si[j] = mi[j]; }
    }

    // recover unbiased sigmoid: s = v - bias[idx]  (<=2^-23 abs deviation)
    float sw8[8];
    float wsum = 0.0f;
    #pragma unroll
    for (int k = 0; k < K_TOP; k++) {
        sw8[k] = sv[k] - __ldg(bias + si[k]);
        wsum += sw8[k];
    }
    const float scale = 2.5f / wsum;

    // lane k writes slot k (all lanes hold identical results)
    #pragma unroll
    for (int k = 0; k < K_TOP; k++) {
        if (lane == k) {
            const size_t o = (size_t)t * K_TOP + k;
            const float wfin = sw8[k] * scale;
            if (mode == 2) {   // all-float32 concatenated layout
                ((float*)w_out)[o]   = wfin;
                ((float*)idx_out)[o] = (float)si[k];
                atomicAdd((float*)cnt_out + si[k], 1.0f);
            } else {           // byte-concat: f32 weights | i64 indices | i32 counts
                ((float*)w_out)[o]       = wfin;
                ((long long*)idx_out)[o] = (long long)si[k];
                atomicAdd((int*)cnt_out + si[k], 1);
            }
        }
    }
}

// ---------------- launch ----------------
extern "C" void kernel_launch(void* const* d_in, const int* in_sizes, int n_in,
                              void* d_out, int out_size)
{
    const float* x    = (const float*)d_in[0];
    const float* W    = (const float*)d_in[1];
    const float* bias = (const float*)d_in[2];

    char* base = (char*)d_out;
    const size_t TK = (size_t)T_TOK * K_TOP;   // 65536

    int mode;
    void *w_out, *idx_out, *cnt_out;
    if (out_size == (int)(TK + TK + E_EXP)) {
        // 131328 elements: single-dtype f32 concat (JAX promotion, x64 off)
        mode = 2;
        w_out   = base;
        idx_out = base + TK * 4;
        cnt_out = base + 2 * TK * 4;
    } else {
        // byte-concatenated outputs: f32 weights | i64 indices | i32 counts
        mode = 0;
        w_out   = base;
        idx_out = base + TK * 4;
        cnt_out = base + TK * 4 + TK * 8;
    }

    dim3 grid(E_EXP / BN, T_TOK / BM);   // (2, 64) = 128 CTAs
    gemm_kernel<<<grid, 256>>>(x, W, g_logits, cnt_out, mode);

    route_kernel<<<T_TOK / 8, 256>>>(g_logits, bias, w_out, idx_out, cnt_out, mode);
}